// round 15
// baseline (speedup 1.0000x reference)
#include <cuda_runtime.h>
#include <cuda_bf16.h>
#include <math.h>

#define IMG_H 512
#define IMG_W 640
#define HW (IMG_H * IMG_W)            // 327680
#define FXc 500.0f
#define FYc 500.0f
#define CXc 320.0f
#define CYc 256.0f

#define PRJ_TPB 256
#define PPT 4
#define SLOTS 8
#define OVCAP 8192
#define LMAX 48                       // overflow-pixel local sort cap

typedef unsigned long long u64;
typedef unsigned int u32;

// ---------------- device scratch ----------------
// g_cnt: [0..HW) per-pixel counts | [HW] overflow count
__device__ u32 g_cnt[HW + 2];
// SoA planes: slot n for pixel p at [n*HW + p]
__device__ u64 g_key[(size_t)SLOTS * HW];     // 21MB, NOT zeroed (counts gate)
__device__ float4 g_pay[(size_t)SLOTS * HW];  // {w, f0, f1, f2}, 42MB
__device__ u64 g_ovk[OVCAP];
__device__ u32 g_ovp[OVCAP];

// key: (zinv << 32) | (idx << 3) | slot_tag.
// Ascending u64 == (z desc, idx asc); tag bits never decide (idx unique).
__device__ __forceinline__ u64 pack_key(float z, u32 idx)
{
    return ((u64)(0xFFFFFFFFu - __float_as_uint(z)) << 32) | ((u64)idx << 3);
}
__device__ __forceinline__ float key_z(u64 k)
{
    return __uint_as_float(0xFFFFFFFFu - (u32)(k >> 32));
}
__device__ __forceinline__ u32 key_idx(u64 k)
{
    return ((u32)k) >> 3;
}

// ---------------- pass 1: project 4 pts/thread + payload scatter ----------
// Projection arithmetic bit-identical to R1 (measured best):
// separate __fmul_rn/__fadd_rn, NO fma contraction.
__global__ void project_scatter_kernel(const float4* __restrict__ means4,
                                       const float* __restrict__ means,
                                       const float4* __restrict__ opac4,
                                       const float* __restrict__ opac,
                                       const float* __restrict__ feats,
                                       const float* __restrict__ pose, int n)
{
    int tbase = (blockIdx.x * blockDim.x + threadIdx.x) * PPT;
    if (tbase >= n) return;

    float m[PPT][3];
    float wv[PPT];
#pragma unroll
    for (int q = 0; q < PPT; q++) { m[q][0] = 0.0f; m[q][1] = 0.0f; m[q][2] = -1.0f; wv[q] = 0.0f; }
    if (tbase + PPT <= n) {
        int v = tbase >> 2;
        float4 a = means4[3 * v + 0];
        float4 b = means4[3 * v + 1];
        float4 c = means4[3 * v + 2];
        m[0][0] = a.x; m[0][1] = a.y; m[0][2] = a.z;
        m[1][0] = a.w; m[1][1] = b.x; m[1][2] = b.y;
        m[2][0] = b.z; m[2][1] = b.w; m[2][2] = c.x;
        m[3][0] = c.y; m[3][1] = c.z; m[3][2] = c.w;
        float4 o = opac4[v];
        wv[0] = o.x; wv[1] = o.y; wv[2] = o.z; wv[3] = o.w;
    } else {
        for (int q = 0; q < PPT; q++)
            if (tbase + q < n) {
                m[q][0] = means[3 * (tbase + q) + 0];
                m[q][1] = means[3 * (tbase + q) + 1];
                m[q][2] = means[3 * (tbase + q) + 2];
                wv[q] = opac[tbase + q];
            }
    }

#pragma unroll
    for (int q = 0; q < PPT; q++) {
        float m0 = m[q][0], m1 = m[q][1], m2 = m[q][2];
        // pose is identity: exact regardless of order
        float pc0 = m0 * pose[0] + m1 * pose[1] + m2 * pose[2]  + pose[3];
        float pc1 = m0 * pose[4] + m1 * pose[5] + m2 * pose[6]  + pose[7];
        float z   = m0 * pose[8] + m1 * pose[9] + m2 * pose[10] + pose[11];
        // IEEE rn div/mul/add, NO fma (matches reference; measured best)
        float x = __fadd_rn(__fmul_rn(__fdiv_rn(pc0, z), FXc), CXc);
        float y = __fadd_rn(__fmul_rn(__fdiv_rn(pc1, z), FYc), CYc);
        bool ok = (tbase + q < n) && (x >= 0.0f) && (x < (float)IMG_W) &&
                  (y >= 0.0f) && (y < (float)IMG_H) && (z > 0.0f);
        if (ok) {
            u32 i = (u32)(tbase + q);
            u32 pid = (u32)((int)floorf(y) * IMG_W + (int)floorf(x));
            u64 key = pack_key(z, i);
            u32 pos = atomicAdd(&g_cnt[pid], 1u);
            if (pos < SLOTS) {
                float f0 = feats[3 * i + 0];
                float f1 = feats[3 * i + 1];
                float f2 = feats[3 * i + 2];
                g_key[(size_t)pos * HW + pid] = key | (u64)pos;
                g_pay[(size_t)pos * HW + pid] = make_float4(wv[q], f0, f1, f2);
            } else {
                u32 o = atomicAdd(&g_cnt[HW], 1u);
                if (o < OVCAP) { g_ovk[o] = key; g_ovp[o] = pid; }
            }
        }
    }
}

// ---------------- fused sort + exact compositing render -------------------
// Sorted order: ascending u64 key == (z desc, idx asc) == reference lexsort.
// Exact compositing: T_i = prod_{j>i}(1 - w_j); contrib_i = w_i * T_i.
// Compositing operand bits and order identical to R13 -> output bit-identical.
#define CSW(a, b) { u64 _lo = (a) < (b) ? (a) : (b); \
                    u64 _hi = (a) < (b) ? (b) : (a); (a) = _lo; (b) = _hi; }

__global__ void __launch_bounds__(256, 8)
render_kernel(const float* __restrict__ opac,
              const float* __restrict__ feats,
              float* __restrict__ out)
{
    int p = blockIdx.x * blockDim.x + threadIdx.x;
    if (p >= HW) return;
    u32 k = g_cnt[p];
    u64 s0 = g_key[p];               // speculative (valid iff k>=1), coalesced
    float4 pay0 = g_pay[p];          // speculative payload, coalesced

    float img0 = 0.0f, img1 = 0.0f, img2 = 0.0f;
    float dep = 0.0f;
    float Lsum = 0.0f;

    if (k == 1) {
        float wv = pay0.x;
        img0 = wv * pay0.y;
        img1 = wv * pay0.z;
        img2 = wv * pay0.w;
        dep  = wv * key_z(s0);
        Lsum = log1pf(-wv);
    } else if (k > 1 && k <= 4) {
        u64 a[4];
        a[0] = s0;
#pragma unroll
        for (int i = 1; i < 4; i++)
            a[i] = ((u32)i < k) ? g_key[(size_t)i * HW + p] : ~0ull;
        CSW(a[0], a[1]); CSW(a[2], a[3]);
        CSW(a[0], a[2]); CSW(a[1], a[3]);
        CSW(a[1], a[2]);
        float T = 1.0f;
#pragma unroll
        for (int i = 3; i >= 0; i--) {
            if ((u32)i < k) {
                u32 tag = (u32)a[i] & 7u;
                float4 pay = g_pay[(size_t)tag * HW + p];
                float wv = pay.x;
                float contrib = wv * T;
                img0 += contrib * pay.y;
                img1 += contrib * pay.z;
                img2 += contrib * pay.w;
                dep  += contrib * key_z(a[i]);
                Lsum += log1pf(-wv);
                T *= (1.0f - wv);
            }
        }
    } else if (k > 4 && k <= 8) {
        u64 a[8];
        a[0] = s0;
#pragma unroll
        for (int i = 1; i < 8; i++)
            a[i] = ((u32)i < k) ? g_key[(size_t)i * HW + p] : ~0ull;
        // Batcher odd-even merge sort, 8 inputs, 19 CEs
        CSW(a[0], a[1]); CSW(a[2], a[3]); CSW(a[4], a[5]); CSW(a[6], a[7]);
        CSW(a[0], a[2]); CSW(a[1], a[3]); CSW(a[4], a[6]); CSW(a[5], a[7]);
        CSW(a[1], a[2]); CSW(a[5], a[6]);
        CSW(a[0], a[4]); CSW(a[1], a[5]); CSW(a[2], a[6]); CSW(a[3], a[7]);
        CSW(a[2], a[4]); CSW(a[3], a[5]);
        CSW(a[1], a[2]); CSW(a[3], a[4]); CSW(a[5], a[6]);
        float T = 1.0f;
#pragma unroll
        for (int i = 7; i >= 0; i--) {
            if ((u32)i < k) {
                u32 tag = (u32)a[i] & 7u;
                float4 pay = g_pay[(size_t)tag * HW + p];
                float wv = pay.x;
                float contrib = wv * T;
                img0 += contrib * pay.y;
                img1 += contrib * pay.z;
                img2 += contrib * pay.w;
                dep  += contrib * key_z(a[i]);
                Lsum += log1pf(-wv);
                T *= (1.0f - wv);
            }
        }
    } else if (k > 8) {
        // overflow pixel (expected ~0-2 per frame): merge slots + overflow,
        // recover idx from keys and gather opac/feats directly.
        u64 list[LMAX];
        int mcount = 0;
        list[mcount++] = s0;
        for (int i = 1; i < SLOTS; i++)
            list[mcount++] = g_key[(size_t)i * HW + p];
        u32 ovn = g_cnt[HW];
        if (ovn > OVCAP) ovn = OVCAP;
        for (u32 j = 0; j < ovn; j++)
            if (g_ovp[j] == (u32)p && mcount < LMAX) list[mcount++] = g_ovk[j];
        // insertion sort ascending (tag bits don't affect order: idx unique)
        for (int i = 1; i < mcount; i++) {
            u64 key = list[i];
            int j = i - 1;
            while (j >= 0 && list[j] > key) { list[j + 1] = list[j]; j--; }
            list[j + 1] = key;
        }
        float T = 1.0f;
        for (int i = mcount - 1; i >= 0; i--) {
            u64 key = list[i];
            u32 idx = key_idx(key);
            float wv = opac[idx];
            float contrib = wv * T;
            img0 += contrib * feats[3 * idx + 0];
            img1 += contrib * feats[3 * idx + 1];
            img2 += contrib * feats[3 * idx + 2];
            dep  += contrib * key_z(key);
            Lsum += log1pf(-wv);
            T *= (1.0f - wv);
        }
    }

    out[0 * HW + p] = img0;
    out[1 * HW + p] = img1;
    out[2 * HW + p] = img2;
    out[3 * HW + p] = dep;
    out[4 * HW + p] = 1.0f - expf(Lsum);
}

// ---------------- launch: 3 graph nodes ----------------
extern "C" void kernel_launch(void* const* d_in, const int* in_sizes, int n_in,
                              void* d_out, int out_size)
{
    const float* means = (const float*)d_in[0];
    const float* opac  = (const float*)d_in[1];
    const float* feats = (const float*)d_in[2];
    const float* pose  = (const float*)d_in[3];
    float* out = (float*)d_out;

    int n = in_sizes[0] / 3;

    void* cnt_addr = nullptr; cudaGetSymbolAddress(&cnt_addr, g_cnt);
    cudaMemsetAsync(cnt_addr, 0, (HW + 2) * sizeof(u32), 0);

    int npt = (n + PPT - 1) / PPT;
    project_scatter_kernel<<<(npt + PRJ_TPB - 1) / PRJ_TPB, PRJ_TPB>>>(
        (const float4*)means, means, (const float4*)opac, opac, feats, pose, n);
    render_kernel<<<(HW + 255) / 256, 256>>>(opac, feats, out);
}

// round 16
// speedup vs baseline: 1.2751x; 1.2751x over previous
#include <cuda_runtime.h>
#include <cuda_bf16.h>
#include <math.h>

#define IMG_H 512
#define IMG_W 640
#define HW (IMG_H * IMG_W)            // 327680
#define FXc 500.0f
#define FYc 500.0f
#define CXc 320.0f
#define CYc 256.0f

#define PRJ_TPB 256
#define PPT 4
#define SLOTS 8
#define OVCAP 8192
#define LMAX 48                       // overflow-pixel local sort cap

typedef unsigned long long u64;
typedef unsigned int u32;

// ---------------- device scratch ----------------
// g_cnt: [0..HW) per-pixel counts | [HW] overflow count
__device__ u32 g_cnt[HW + 2];
// SoA: slot n for pixel p at g_slot[n*HW + p]  (coalesced render reads)
__device__ u64 g_slot[(size_t)SLOTS * HW];   // 21MB, NOT zeroed (counts gate)
__device__ u64 g_ovk[OVCAP];
__device__ u32 g_ovp[OVCAP];

// key: ascending u64 sort == (z desc, idx asc). z>0 so float bits monotonic.
__device__ __forceinline__ u64 pack_key(float z, u32 idx)
{
    return ((u64)(0xFFFFFFFFu - __float_as_uint(z)) << 32) | (u64)idx;
}
__device__ __forceinline__ float key_z(u64 k)
{
    return __uint_as_float(0xFFFFFFFFu - (u32)(k >> 32));
}

// ---------------- pass 1: project 4 pts/thread + direct slot scatter ------
// (R13 verbatim — measured 12us; payload scatter measured WORSE, reverted)
// Projection arithmetic bit-identical to R1 (measured best):
// separate __fmul_rn/__fadd_rn, NO fma contraction.
__global__ void project_scatter_kernel(const float4* __restrict__ means4,
                                       const float* __restrict__ means,
                                       const float* __restrict__ pose, int n)
{
    int tbase = (blockIdx.x * blockDim.x + threadIdx.x) * PPT;
    if (tbase >= n) return;

    float m[PPT][3];
#pragma unroll
    for (int q = 0; q < PPT; q++) { m[q][0] = 0.0f; m[q][1] = 0.0f; m[q][2] = -1.0f; }
    if (tbase + PPT <= n) {
        int v = tbase >> 2;
        float4 a = means4[3 * v + 0];
        float4 b = means4[3 * v + 1];
        float4 c = means4[3 * v + 2];
        m[0][0] = a.x; m[0][1] = a.y; m[0][2] = a.z;
        m[1][0] = a.w; m[1][1] = b.x; m[1][2] = b.y;
        m[2][0] = b.z; m[2][1] = b.w; m[2][2] = c.x;
        m[3][0] = c.y; m[3][1] = c.z; m[3][2] = c.w;
    } else {
        for (int q = 0; q < PPT; q++)
            if (tbase + q < n) {
                m[q][0] = means[3 * (tbase + q) + 0];
                m[q][1] = means[3 * (tbase + q) + 1];
                m[q][2] = means[3 * (tbase + q) + 2];
            }
    }

#pragma unroll
    for (int q = 0; q < PPT; q++) {
        float m0 = m[q][0], m1 = m[q][1], m2 = m[q][2];
        // pose is identity: exact regardless of order
        float pc0 = m0 * pose[0] + m1 * pose[1] + m2 * pose[2]  + pose[3];
        float pc1 = m0 * pose[4] + m1 * pose[5] + m2 * pose[6]  + pose[7];
        float z   = m0 * pose[8] + m1 * pose[9] + m2 * pose[10] + pose[11];
        // IEEE rn div/mul/add, NO fma (matches reference; measured best)
        float x = __fadd_rn(__fmul_rn(__fdiv_rn(pc0, z), FXc), CXc);
        float y = __fadd_rn(__fmul_rn(__fdiv_rn(pc1, z), FYc), CYc);
        bool ok = (tbase + q < n) && (x >= 0.0f) && (x < (float)IMG_W) &&
                  (y >= 0.0f) && (y < (float)IMG_H) && (z > 0.0f);
        if (ok) {
            u32 pid = (u32)((int)floorf(y) * IMG_W + (int)floorf(x));
            u64 key = pack_key(z, (u32)(tbase + q));
            u32 pos = atomicAdd(&g_cnt[pid], 1u);
            if (pos < SLOTS) {
                g_slot[(size_t)pos * HW + pid] = key;
            } else {
                u32 o = atomicAdd(&g_cnt[HW], 1u);
                if (o < OVCAP) { g_ovk[o] = key; g_ovp[o] = pid; }
            }
        }
    }
}

// ---------------- fused sort + exact compositing render -------------------
// Gathers issued BEFORE the sort (indices don't depend on order) -> the
// sorting network hides gather latency. Tuple-carrying compare-swaps on the
// k<=4 path; k in (4,8] keeps the key-only network (register watermark).
// Sorted order: ascending u64 key == (z desc, idx asc) == reference lexsort.
// Compositing values/order identical to R13 -> output bit-identical.
#define CSW(a, b) { u64 _lo = (a) < (b) ? (a) : (b); \
                    u64 _hi = (a) < (b) ? (b) : (a); (a) = _lo; (b) = _hi; }

#define CSWT(i, j) { \
    bool _sw = a[i] > a[j]; \
    u64 _tk = _sw ? a[j] : a[i];   a[j] = _sw ? a[i] : a[j];   a[i] = _tk; \
    float _tw = _sw ? w[j] : w[i]; w[j] = _sw ? w[i] : w[j];   w[i] = _tw; \
    float _t0 = _sw ? f0[j] : f0[i]; f0[j] = _sw ? f0[i] : f0[j]; f0[i] = _t0; \
    float _t1 = _sw ? f1[j] : f1[i]; f1[j] = _sw ? f1[i] : f1[j]; f1[i] = _t1; \
    float _t2 = _sw ? f2[j] : f2[i]; f2[j] = _sw ? f2[i] : f2[j]; f2[i] = _t2; }

__global__ void __launch_bounds__(256, 6)
render_kernel(const float* __restrict__ opac,
              const float* __restrict__ feats,
              float* __restrict__ out)
{
    int p = blockIdx.x * blockDim.x + threadIdx.x;
    if (p >= HW) return;
    u32 k = g_cnt[p];
    u64 s0 = g_slot[p];              // speculative (valid iff k>=1), coalesced

    float img0 = 0.0f, img1 = 0.0f, img2 = 0.0f;
    float dep = 0.0f;
    float Lsum = 0.0f;

    if (k == 1) {
        u32 idx = (u32)s0;
        float wv = opac[idx];
        img0 = wv * feats[3 * idx + 0];
        img1 = wv * feats[3 * idx + 1];
        img2 = wv * feats[3 * idx + 2];
        dep  = wv * key_z(s0);
        Lsum = log1pf(-wv);
    } else if (k == 2) {
        u64 a0 = s0;
        u64 a1 = g_slot[(size_t)HW + p];
        u32 i0 = (u32)a0, i1 = (u32)a1;
        // gathers issued before the compare (independent)
        float wA = opac[i0], wB = opac[i1];
        float fA0 = feats[3 * i0 + 0], fA1 = feats[3 * i0 + 1], fA2 = feats[3 * i0 + 2];
        float fB0 = feats[3 * i1 + 0], fB1 = feats[3 * i1 + 1], fB2 = feats[3 * i1 + 2];
        if (a0 > a1) {
            u64 tk = a0; a0 = a1; a1 = tk;
            float t;
            t = wA; wA = wB; wB = t;
            t = fA0; fA0 = fB0; fB0 = t;
            t = fA1; fA1 = fB1; fB1 = t;
            t = fA2; fA2 = fB2; fB2 = t;
        }
        // back-to-front: element 1 then element 0
        float T = 1.0f;
        float contrib = wB * T;
        img0 += contrib * fB0; img1 += contrib * fB1; img2 += contrib * fB2;
        dep  += contrib * key_z(a1);
        Lsum += log1pf(-wB);
        T *= (1.0f - wB);
        contrib = wA * T;
        img0 += contrib * fA0; img1 += contrib * fA1; img2 += contrib * fA2;
        dep  += contrib * key_z(a0);
        Lsum += log1pf(-wA);
        T *= (1.0f - wA);
    } else if (k > 2 && k <= 4) {
        u64 a[4];
        float w[4], f0[4], f1[4], f2[4];
        a[0] = s0;
#pragma unroll
        for (int i = 1; i < 4; i++)
            a[i] = ((u32)i < k) ? g_slot[(size_t)i * HW + p] : ~0ull;
        // gathers BEFORE the network (independent -> MLP)
#pragma unroll
        for (int i = 0; i < 4; i++) {
            u32 idx = (u32)a[i];
            bool v = ((u32)i < k);
            w[i]  = v ? opac[idx] : 0.0f;
            f0[i] = v ? feats[3 * idx + 0] : 0.0f;
            f1[i] = v ? feats[3 * idx + 1] : 0.0f;
            f2[i] = v ? feats[3 * idx + 2] : 0.0f;
        }
        // tuple-carrying 4-input network (pads sort to the end: key ~0)
        CSWT(0, 1); CSWT(2, 3);
        CSWT(0, 2); CSWT(1, 3);
        CSWT(1, 2);
        float T = 1.0f;
#pragma unroll
        for (int i = 3; i >= 0; i--) {
            if ((u32)i < k) {
                float contrib = w[i] * T;
                img0 += contrib * f0[i];
                img1 += contrib * f1[i];
                img2 += contrib * f2[i];
                dep  += contrib * key_z(a[i]);
                Lsum += log1pf(-w[i]);
                T *= (1.0f - w[i]);
            }
        }
    } else if (k > 4 && k <= 8) {
        // rare (~1.6% of pixels): key-only network, post-sort gather (R13)
        u64 a[8];
        a[0] = s0;
#pragma unroll
        for (int i = 1; i < 8; i++)
            a[i] = ((u32)i < k) ? g_slot[(size_t)i * HW + p] : ~0ull;
        CSW(a[0], a[1]); CSW(a[2], a[3]); CSW(a[4], a[5]); CSW(a[6], a[7]);
        CSW(a[0], a[2]); CSW(a[1], a[3]); CSW(a[4], a[6]); CSW(a[5], a[7]);
        CSW(a[1], a[2]); CSW(a[5], a[6]);
        CSW(a[0], a[4]); CSW(a[1], a[5]); CSW(a[2], a[6]); CSW(a[3], a[7]);
        CSW(a[2], a[4]); CSW(a[3], a[5]);
        CSW(a[1], a[2]); CSW(a[3], a[4]); CSW(a[5], a[6]);
        float w[8];
#pragma unroll
        for (int i = 0; i < 8; i++)
            w[i] = ((u32)i < k) ? opac[(u32)a[i]] : 0.0f;
        float T = 1.0f;
#pragma unroll
        for (int i = 7; i >= 0; i--) {
            if ((u32)i < k) {
                float contrib = w[i] * T;
                u32 idx = (u32)a[i];
                img0 += contrib * feats[3 * idx + 0];
                img1 += contrib * feats[3 * idx + 1];
                img2 += contrib * feats[3 * idx + 2];
                dep  += contrib * key_z(a[i]);
                Lsum += log1pf(-w[i]);
                T *= (1.0f - w[i]);
            }
        }
    } else if (k > 8) {
        // overflow pixel (expected ~0-2 per frame): merge slots + overflow
        u64 list[LMAX];
        int mcount = 0;
        list[mcount++] = s0;
        for (int i = 1; i < SLOTS; i++)
            list[mcount++] = g_slot[(size_t)i * HW + p];
        u32 ovn = g_cnt[HW];
        if (ovn > OVCAP) ovn = OVCAP;
        for (u32 j = 0; j < ovn; j++)
            if (g_ovp[j] == (u32)p && mcount < LMAX) list[mcount++] = g_ovk[j];
        for (int i = 1; i < mcount; i++) {
            u64 key = list[i];
            int j = i - 1;
            while (j >= 0 && list[j] > key) { list[j + 1] = list[j]; j--; }
            list[j + 1] = key;
        }
        float T = 1.0f;
        for (int i = mcount - 1; i >= 0; i--) {
            u64 key = list[i];
            u32 idx = (u32)key;
            float wv = opac[idx];
            float contrib = wv * T;
            img0 += contrib * feats[3 * idx + 0];
            img1 += contrib * feats[3 * idx + 1];
            img2 += contrib * feats[3 * idx + 2];
            dep  += contrib * key_z(key);
            Lsum += log1pf(-wv);
            T *= (1.0f - wv);
        }
    }

    out[0 * HW + p] = img0;
    out[1 * HW + p] = img1;
    out[2 * HW + p] = img2;
    out[3 * HW + p] = dep;
    out[4 * HW + p] = 1.0f - expf(Lsum);
}

// ---------------- launch: 3 graph nodes ----------------
extern "C" void kernel_launch(void* const* d_in, const int* in_sizes, int n_in,
                              void* d_out, int out_size)
{
    const float* means = (const float*)d_in[0];
    const float* opac  = (const float*)d_in[1];
    const float* feats = (const float*)d_in[2];
    const float* pose  = (const float*)d_in[3];
    float* out = (float*)d_out;

    int n = in_sizes[0] / 3;

    void* cnt_addr = nullptr; cudaGetSymbolAddress(&cnt_addr, g_cnt);
    cudaMemsetAsync(cnt_addr, 0, (HW + 2) * sizeof(u32), 0);

    int npt = (n + PPT - 1) / PPT;
    project_scatter_kernel<<<(npt + PRJ_TPB - 1) / PRJ_TPB, PRJ_TPB>>>(
        (const float4*)means, means, pose, n);
    render_kernel<<<(HW + 255) / 256, 256>>>(opac, feats, out);
}